// round 14
// baseline (speedup 1.0000x reference)
#include <cuda_runtime.h>
#include <cuda_fp16.h>
#include <cstdint>

#define NN 100000
#define NE 1600000
#define FF 128
#define GG 64
#define EPSV 1e-5f

#define OUT_FLAT ((size_t)NN * FF)
#define OUT_EI   (OUT_FLAT + (size_t)GG * FF)
#define OUT_EW   (OUT_EI + (size_t)2 * NE)
#define OUT_B    (OUT_EW + (size_t)NE)

#define SCAN_B 98
#define SCAN_T 256
#define SCAN_I 4

#define FIXS 268435456.0f               /* 2^28 */
#define FIXR 3.7252902984619140625e-9f /* 2^-28 */

#define INIT_B   391
#define ZERO_B   32
#define BOUNDS_B 391
#define DEG_B    6250
#define TAILV    1225000
#define TAIL_B   4786
#define GEMM_B   782
#define CSR_B    6250

// Scratch
__device__ unsigned long long g_pack[NN];
__device__ unsigned short g_slot[NE];
__device__ float  g_dis[NN];
__device__ int    g_off[NN + 1];
__device__ int    g_bsum[SCAN_B];           // -1 sentinel, then block totals
__device__ int2   g_csr[NE];                // {src, norm bits}
__device__ __half g_xw[(size_t)NN * FF];
__device__ __half g_hh[(size_t)NN * FF];
__device__ int    g_starts[GG + 1];
__device__ float  g_sum[GG * FF];
__device__ float  g_sq[GG * FF];

__device__ __forceinline__ unsigned f2h2(float a, float b) {
    __half2 h = __floats2half2_rn(a, b);
    return *(unsigned*)&h;
}

// ============ 1. fused: init ∥ zero ∥ bounds ∥ bsum-sentinel ============
__global__ void k_pre(const int* __restrict__ batch, float* __restrict__ out_flat) {
    int blk = blockIdx.x;
    if (blk < INIT_B) {
        int i = blk * 256 + threadIdx.x;
        if (i < NN) g_pack[i] = (unsigned long long)(1u << 28);
        if (blk == 0 && threadIdx.x < SCAN_B) g_bsum[threadIdx.x] = -1;
    } else if (blk < INIT_B + ZERO_B) {
        int i = (blk - INIT_B) * 256 + threadIdx.x;
        g_sum[i] = 0.0f; g_sq[i] = 0.0f; out_flat[i] = 0.0f;
    } else {
        int i = (blk - INIT_B - ZERO_B) * 256 + threadIdx.x;
        if (i >= NN) return;
        int bv = batch[i];
        int prev = (i == 0) ? -1 : batch[i - 1];
        for (int g = prev + 1; g <= bv; ++g) g_starts[g] = i;
        if (i == NN - 1)
            for (int g = bv + 1; g <= GG; ++g) g_starts[g] = NN;
    }
}

// ============ 2. fused: deg ∥ tail ∥ HMMA gemm ============
__global__ __launch_bounds__(256) void k_degtailgemm(
        const int* __restrict__ ei, const float* __restrict__ ew,
        const int* __restrict__ batch, float* __restrict__ out,
        const float* __restrict__ X, const float* __restrict__ W) {
    __shared__ __half2 Wp[64][136];
    int blk = blockIdx.x;
    int tid = threadIdx.x;

    if (blk < DEG_B) {
        int e = blk * 256 + tid;
        int d = ei[NE + e];
        unsigned long long q = (unsigned long long)__float2uint_rn(ew[e] * FIXS);
        unsigned long long old = atomicAdd(&g_pack[d], (1ull << 40) | q);
        g_slot[e] = (unsigned short)(old >> 40);
        return;
    }
    if (blk < DEG_B + TAIL_B) {
        int vt = (blk - DEG_B) * 256 + tid;
        if (vt >= TAILV) return;
        if (vt < 800000) {
            int j = vt * 4;
            int4 v = *(const int4*)(ei + j);
            float4 o = make_float4((float)v.x, (float)v.y, (float)v.z, (float)v.w);
            *(float4*)(out + OUT_EI + j) = o;
        } else if (vt < 1200000) {
            int j = (vt - 800000) * 4;
            *(float4*)(out + OUT_EW + j) = *(const float4*)(ew + j);
        } else {
            int j = (vt - 1200000) * 4;
            int4 v = *(const int4*)(batch + j);
            float4 o = make_float4((float)v.x, (float)v.y, (float)v.z, (float)v.w);
            *(float4*)(out + OUT_B + j) = o;
        }
        return;
    }

    // ---- GEMM tile ----
    int gb = blk - DEG_B - TAIL_B;
    int r0 = gb * 128;
    for (int idx = tid; idx < 64 * 32; idx += 256) {
        int kp = idx >> 5;
        int n4 = (idx & 31) * 4;
        float4 w0 = *(const float4*)(W + (size_t)(2 * kp) * FF + n4);
        float4 w1 = *(const float4*)(W + (size_t)(2 * kp + 1) * FF + n4);
        Wp[kp][n4 + 0] = __floats2half2_rn(w0.x, w1.x);
        Wp[kp][n4 + 1] = __floats2half2_rn(w0.y, w1.y);
        Wp[kp][n4 + 2] = __floats2half2_rn(w0.z, w1.z);
        Wp[kp][n4 + 3] = __floats2half2_rn(w0.w, w1.w);
    }
    __syncthreads();

    int warp = tid >> 5, lane = tid & 31;
    int gid = lane >> 2;
    int tig = lane & 3;
    int r_lo = r0 + warp * 16 + gid;
    int r_hi = r_lo + 8;
    bool vlo = r_lo < NN, vhi = r_hi < NN;
    const float2* plo = (const float2*)(X + (size_t)r_lo * FF);
    const float2* phi = (const float2*)(X + (size_t)r_hi * FF);
    int c2 = tig;

    float acc[16][4];
#pragma unroll
    for (int nt = 0; nt < 16; ++nt)
#pragma unroll
        for (int q = 0; q < 4; ++q) acc[nt][q] = 0.0f;

#pragma unroll
    for (int kk = 0; kk < 8; ++kk) {
        int kb = kk * 8;
        float2 z = make_float2(0.f, 0.f);
        float2 f0 = vlo ? plo[kb + c2]     : z;
        float2 f1 = vhi ? phi[kb + c2]     : z;
        float2 f2 = vlo ? plo[kb + c2 + 4] : z;
        float2 f3 = vhi ? phi[kb + c2 + 4] : z;
        unsigned a0 = f2h2(f0.x, f0.y);
        unsigned a1 = f2h2(f1.x, f1.y);
        unsigned a2 = f2h2(f2.x, f2.y);
        unsigned a3 = f2h2(f3.x, f3.y);
        int kp = kb + tig;
#pragma unroll
        for (int nt = 0; nt < 16; ++nt) {
            int n = nt * 8 + gid;
            unsigned b0 = *(unsigned*)&Wp[kp][n];
            unsigned b1 = *(unsigned*)&Wp[kp + 4][n];
            asm volatile(
                "mma.sync.aligned.m16n8k16.row.col.f32.f16.f16.f32 "
                "{%0,%1,%2,%3},{%4,%5,%6,%7},{%8,%9},{%0,%1,%2,%3};"
                : "+f"(acc[nt][0]), "+f"(acc[nt][1]), "+f"(acc[nt][2]), "+f"(acc[nt][3])
                : "r"(a0), "r"(a1), "r"(a2), "r"(a3), "r"(b0), "r"(b1));
        }
    }

#pragma unroll
    for (int nt = 0; nt < 16; ++nt) {
        int col = nt * 8 + tig * 2;
        if (vlo) {
            __half2 h = __floats2half2_rn(acc[nt][0], acc[nt][1]);
            *(__half2*)(g_xw + (size_t)r_lo * FF + col) = h;
        }
        if (vhi) {
            __half2 h = __floats2half2_rn(acc[nt][2], acc[nt][3]);
            *(__half2*)(g_xw + (size_t)r_hi * FF + col) = h;
        }
    }
}

// ============ 3. single-launch scan (decoupled aggregate posting) ============
__global__ __launch_bounds__(SCAN_T) void k_scan() {
    __shared__ int sh[SCAN_T];
    __shared__ int s_base;
    int t = threadIdx.x;
    int base = blockIdx.x * SCAN_T * SCAN_I + t * SCAN_I;
    int c[SCAN_I];
    int s = 0;
#pragma unroll
    for (int k = 0; k < SCAN_I; ++k) {
        int i = base + k;
        if (i < NN) {
            unsigned long long p = g_pack[i];
            c[k] = (int)(p >> 40);
            g_dis[i] = rsqrtf((float)(p & 0xFFFFFFFFFFull) * FIXR);
            s += c[k];
        } else c[k] = 0;
    }
    sh[t] = s;
    if (t == 0) s_base = 0;
    __syncthreads();
    // inclusive scan
    for (int off = 1; off < SCAN_T; off <<= 1) {
        int v = (t >= off) ? sh[t - off] : 0;
        __syncthreads();
        sh[t] += v;
        __syncthreads();
    }
    // post this block's total
    if (t == 0) {
        *(volatile int*)&g_bsum[blockIdx.x] = sh[SCAN_T - 1];
    }
    // spin-collect predecessors' totals (all 98 blocks are resident: 98 < 148 SMs)
    if (t < blockIdx.x) {
        int v;
        do { v = *(volatile int*)&g_bsum[t]; } while (v < 0);
        atomicAdd(&s_base, v);
    }
    __syncthreads();
    int run = s_base + sh[t] - s;      // global exclusive prefix
#pragma unroll
    for (int k = 0; k < SCAN_I; ++k) {
        int i = base + k;
        if (i < NN) g_off[i] = run;
        run += c[k];
    }
    if (blockIdx.x == 0 && t == 0) g_off[NN] = NE;
}

// ============ 4. csr fill (atomic-free) ============
__global__ void k_csr(const int* __restrict__ ei, const float* __restrict__ ew) {
    int e = blockIdx.x * blockDim.x + threadIdx.x;
    if (e >= NE) return;
    int s = ei[e];
    int d = ei[NE + e];
    float nrm = g_dis[s] * ew[e] * g_dis[d];
    int pos = g_off[d] + (int)g_slot[e];
    g_csr[pos] = make_int2(s, __float_as_int(nrm));
}

// 8-feature fp16 fragment accumulate
__device__ __forceinline__ void acc_row8(float* acc, float n, int src, int fl) {
    uint4 r = *((const uint4*)(g_xw + (size_t)src * FF) + fl);
    float2 p0 = __half22float2(*reinterpret_cast<__half2*>(&r.x));
    float2 p1 = __half22float2(*reinterpret_cast<__half2*>(&r.y));
    float2 p2 = __half22float2(*reinterpret_cast<__half2*>(&r.z));
    float2 p3 = __half22float2(*reinterpret_cast<__half2*>(&r.w));
    acc[0] += n * p0.x; acc[1] += n * p0.y;
    acc[2] += n * p1.x; acc[3] += n * p1.y;
    acc[4] += n * p2.x; acc[5] += n * p2.y;
    acc[6] += n * p3.x; acc[7] += n * p3.y;
}

// ============ 5. CSR gather: 2 nodes/warp, meta prefetch pipeline ============
__global__ __launch_bounds__(256) void k_gather(const float* __restrict__ b) {
    int warp = threadIdx.x >> 5;
    int lane = threadIdx.x & 31;
    int half = lane >> 4;
    int fl   = lane & 15;
    int node = blockIdx.x * 16 + warp * 2 + half;
    if (node >= NN) return;
    int f8 = fl * 8;

    float acc[8];
    {
        float dv = g_dis[node];
        float d2 = dv * dv;
        uint4 r = *((const uint4*)(g_xw + (size_t)node * FF) + fl);
        float2 p0 = __half22float2(*reinterpret_cast<__half2*>(&r.x));
        float2 p1 = __half22float2(*reinterpret_cast<__half2*>(&r.y));
        float2 p2 = __half22float2(*reinterpret_cast<__half2*>(&r.z));
        float2 p3 = __half22float2(*reinterpret_cast<__half2*>(&r.w));
        float4 b0 = *(const float4*)(b + f8);
        float4 b1 = *(const float4*)(b + f8 + 4);
        acc[0] = b0.x + d2 * p0.x; acc[1] = b0.y + d2 * p0.y;
        acc[2] = b0.z + d2 * p1.x; acc[3] = b0.w + d2 * p1.y;
        acc[4] = b1.x + d2 * p2.x; acc[5] = b1.y + d2 * p2.y;
        acc[6] = b1.z + d2 * p3.x; acc[7] = b1.w + d2 * p3.y;
    }

    int j = g_off[node], j1 = g_off[node + 1];
    if ((j & 1) && j < j1) {               // peel to int4 alignment
        int2 e = g_csr[j];
        acc_row8(acc, __int_as_float(e.y), e.x, fl);
        ++j;
    }
    int npairs = (j1 - j) >> 1;            // edge pairs via int4
    if (npairs > 0) {
        int4 m = *(const int4*)(g_csr + j);
        for (int p = 0; p < npairs; ++p) {
            int4 cur = m;
            if (p + 1 < npairs)
                m = *(const int4*)(g_csr + j + 2 * (p + 1));   // prefetch next pair
            acc_row8(acc, __int_as_float(cur.y), cur.x, fl);
            acc_row8(acc, __int_as_float(cur.w), cur.z, fl);
        }
        j += 2 * npairs;
    }
    if (j < j1) {
        int2 e = g_csr[j];
        acc_row8(acc, __int_as_float(e.y), e.x, fl);
    }

    uint4 pk;
    pk.x = f2h2(acc[0], acc[1]);
    pk.y = f2h2(acc[2], acc[3]);
    pk.z = f2h2(acc[4], acc[5]);
    pk.w = f2h2(acc[6], acc[7]);
    *((uint4*)(g_hh + (size_t)node * FF) + fl) = pk;
}

// ============ 6. stats ============
__global__ void k_stats() {
    int g = blockIdx.y, c = blockIdx.x, f = threadIdx.x;
    int s = g_starts[g], e = g_starts[g + 1];
    int per = (e - s + gridDim.x - 1) / gridDim.x;
    int i0 = s + c * per;
    int i1 = min(i0 + per, e);
    float s1 = 0.0f, s2 = 0.0f;
    for (int i = i0; i < i1; ++i) {
        float v = __half2float(g_hh[(size_t)i * FF + f]);
        s1 += v; s2 += v * v;
    }
    if (i1 > i0) {
        atomicAdd(&g_sum[g * FF + f], s1);
        atomicAdd(&g_sq[g * FF + f], s2);
    }
}

// ============ 7. final: inline affine + normalize + ReLU + max ============
__global__ void k_final(const float* __restrict__ ms, const float* __restrict__ gnw,
                        const float* __restrict__ gnb,
                        float* __restrict__ out_h, float* __restrict__ out_flat) {
    int g = blockIdx.y, c = blockIdx.x, f = threadIdx.x;
    int s = g_starts[g], e = g_starts[g + 1];

    float cnt = fmaxf((float)(e - s), 1.0f);
    float mean = g_sum[g * FF + f] / cnt;
    float m2 = mean * ms[f];
    float var = g_sq[g * FF + f] / cnt - 2.0f * m2 * mean + m2 * m2;
    var = fmaxf(var, 0.0f);
    float rstd = rsqrtf(var + EPSV);
    float sc = gnw[f] * rstd;
    float sh = gnb[f] - sc * m2;

    int per = (e - s + gridDim.x - 1) / gridDim.x;
    int i0 = s + c * per;
    int i1 = min(i0 + per, e);
    float m = 0.0f;
    for (int i = i0; i < i1; ++i) {
        float hv = __half2float(g_hh[(size_t)i * FF + f]);
        float v = fmaxf(fmaf(hv, sc, sh), 0.0f);
        out_h[(size_t)i * FF + f] = v;
        m = fmaxf(m, v);
    }
    if (i1 > i0) atomicMax((int*)&out_flat[g * FF + f], __float_as_int(m));
}

// ---------------------------------------------------------------------------
extern "C" void kernel_launch(void* const* d_in, const int* in_sizes, int n_in,
                              void* d_out, int out_size) {
    const float* X   = (const float*)d_in[0];
    const int*   ei  = (const int*)d_in[1];
    const int*   bat = (const int*)d_in[2];
    const float* ew  = (const float*)d_in[3];
    const float* W   = (const float*)d_in[4];
    const float* b   = (const float*)d_in[5];
    const float* gnw = (const float*)d_in[6];
    const float* gnb = (const float*)d_in[7];
    const float* gms = (const float*)d_in[8];
    float* out = (float*)d_out;

    k_pre<<<INIT_B + ZERO_B + BOUNDS_B, 256>>>(bat, out + OUT_FLAT);
    k_degtailgemm<<<DEG_B + TAIL_B + GEMM_B, 256>>>(ei, ew, bat, out, X, W);

    k_scan<<<SCAN_B, SCAN_T>>>();
    k_csr<<<CSR_B, 256>>>(ei, ew);

    k_gather<<<(NN + 15) / 16, 256>>>(b);

    dim3 sgrid(16, GG);
    k_stats<<<sgrid, FF>>>();

    dim3 fgrid(32, GG);
    k_final<<<fgrid, FF>>>(gms, gnw, gnb, out, out + OUT_FLAT);
}

// round 15
// speedup vs baseline: 1.0678x; 1.0678x over previous
#include <cuda_runtime.h>
#include <cuda_fp16.h>
#include <cstdint>

#define NN 100000
#define NE 1600000
#define FF 128
#define GG 64
#define EPSV 1e-5f

#define OUT_FLAT ((size_t)NN * FF)
#define OUT_EI   (OUT_FLAT + (size_t)GG * FF)
#define OUT_EW   (OUT_EI + (size_t)2 * NE)
#define OUT_B    (OUT_EW + (size_t)NE)

#define SCAN_B 98
#define SCAN_T 256
#define SCAN_I 4

#define FIXS 268435456.0f               /* 2^28 */
#define FIXR 3.7252902984619140625e-9f /* 2^-28 */

#define INIT_B   391
#define ZERO_B   32
#define BOUNDS_B 391
#define DEG_B    6250
#define TAILV    1225000
#define TAIL_B   4786
#define GEMM_B   782
#define CSR_B    6250

// Scratch
__device__ unsigned long long g_pack[NN];
__device__ unsigned short g_slot[NE];
__device__ float  g_dis[NN];
__device__ int    g_off[NN + 1];
__device__ int    g_bsum[SCAN_B];           // -1 sentinel, then block totals
__device__ int2   g_csr[NE];                // {src, norm bits}
__device__ __half g_xw[(size_t)NN * FF];
__device__ __half g_hh[(size_t)NN * FF];
__device__ int    g_starts[GG + 1];
__device__ float  g_sum[GG * FF];
__device__ float  g_sq[GG * FF];

__device__ __forceinline__ unsigned f2h2(float a, float b) {
    __half2 h = __floats2half2_rn(a, b);
    return *(unsigned*)&h;
}

// ============ 1. fused: init ∥ zero ∥ bounds ∥ bsum-sentinel ============
__global__ void k_pre(const int* __restrict__ batch, float* __restrict__ out_flat) {
    int blk = blockIdx.x;
    if (blk < INIT_B) {
        int i = blk * 256 + threadIdx.x;
        if (i < NN) g_pack[i] = (unsigned long long)(1u << 28);
        if (blk == 0 && threadIdx.x < SCAN_B) g_bsum[threadIdx.x] = -1;
    } else if (blk < INIT_B + ZERO_B) {
        int i = (blk - INIT_B) * 256 + threadIdx.x;
        g_sum[i] = 0.0f; g_sq[i] = 0.0f; out_flat[i] = 0.0f;
    } else {
        int i = (blk - INIT_B - ZERO_B) * 256 + threadIdx.x;
        if (i >= NN) return;
        int bv = batch[i];
        int prev = (i == 0) ? -1 : batch[i - 1];
        for (int g = prev + 1; g <= bv; ++g) g_starts[g] = i;
        if (i == NN - 1)
            for (int g = bv + 1; g <= GG; ++g) g_starts[g] = NN;
    }
}

// ============ 2. fused: deg ∥ vectorized tail ============
__global__ void k_degtail(const int* __restrict__ ei, const float* __restrict__ ew,
                          const int* __restrict__ batch, float* __restrict__ out) {
    int blk = blockIdx.x;
    if (blk < DEG_B) {
        int e = blk * 256 + threadIdx.x;
        int d = ei[NE + e];
        unsigned long long q = (unsigned long long)__float2uint_rn(ew[e] * FIXS);
        unsigned long long old = atomicAdd(&g_pack[d], (1ull << 40) | q);
        g_slot[e] = (unsigned short)(old >> 40);
    } else {
        int vt = (blk - DEG_B) * 256 + threadIdx.x;
        if (vt >= TAILV) return;
        if (vt < 800000) {
            int j = vt * 4;
            int4 v = *(const int4*)(ei + j);
            float4 o = make_float4((float)v.x, (float)v.y, (float)v.z, (float)v.w);
            *(float4*)(out + OUT_EI + j) = o;
        } else if (vt < 1200000) {
            int j = (vt - 800000) * 4;
            *(float4*)(out + OUT_EW + j) = *(const float4*)(ew + j);
        } else {
            int j = (vt - 1200000) * 4;
            int4 v = *(const int4*)(batch + j);
            float4 o = make_float4((float)v.x, (float)v.y, (float)v.z, (float)v.w);
            *(float4*)(out + OUT_B + j) = o;
        }
    }
}

// ============ 3. single-launch scan (decoupled aggregate posting) ============
__global__ __launch_bounds__(SCAN_T) void k_scan() {
    __shared__ int sh[SCAN_T];
    __shared__ int s_base;
    int t = threadIdx.x;
    int base = blockIdx.x * SCAN_T * SCAN_I + t * SCAN_I;
    int c[SCAN_I];
    int s = 0;
#pragma unroll
    for (int k = 0; k < SCAN_I; ++k) {
        int i = base + k;
        if (i < NN) {
            unsigned long long p = g_pack[i];
            c[k] = (int)(p >> 40);
            g_dis[i] = rsqrtf((float)(p & 0xFFFFFFFFFFull) * FIXR);
            s += c[k];
        } else c[k] = 0;
    }
    sh[t] = s;
    if (t == 0) s_base = 0;
    __syncthreads();
    for (int off = 1; off < SCAN_T; off <<= 1) {
        int v = (t >= off) ? sh[t - off] : 0;
        __syncthreads();
        sh[t] += v;
        __syncthreads();
    }
    if (t == 0) {
        *(volatile int*)&g_bsum[blockIdx.x] = sh[SCAN_T - 1];
    }
    // collect predecessors' totals (98 blocks < 148 SMs: all resident, no deadlock)
    if (t < blockIdx.x) {
        int v;
        do { v = *(volatile int*)&g_bsum[t]; } while (v < 0);
        atomicAdd(&s_base, v);
    }
    __syncthreads();
    int run = s_base + sh[t] - s;
#pragma unroll
    for (int k = 0; k < SCAN_I; ++k) {
        int i = base + k;
        if (i < NN) g_off[i] = run;
        run += c[k];
    }
    if (blockIdx.x == 0 && t == 0) g_off[NN] = NE;
}

// ============ 4. fused: HMMA gemm ∥ compact csr fill (R12 pairing) ============
__global__ __launch_bounds__(256) void k_csrgemm(const float* __restrict__ X,
                                                 const float* __restrict__ W,
                                                 const int* __restrict__ ei,
                                                 const float* __restrict__ ew) {
    __shared__ __half2 Wp[64][136];
    int blk = blockIdx.x;
    int tid = threadIdx.x;

    if (blk >= GEMM_B) {
        int e = (blk - GEMM_B) * 256 + tid;
        if (e < NE) {
            int s = ei[e];
            int d = ei[NE + e];
            float nrm = g_dis[s] * ew[e] * g_dis[d];
            int pos = g_off[d] + (int)g_slot[e];
            g_csr[pos] = make_int2(s, __float_as_int(nrm));
        }
        return;
    }

    int r0 = blk * 128;
    for (int idx = tid; idx < 64 * 32; idx += 256) {
        int kp = idx >> 5;
        int n4 = (idx & 31) * 4;
        float4 w0 = *(const float4*)(W + (size_t)(2 * kp) * FF + n4);
        float4 w1 = *(const float4*)(W + (size_t)(2 * kp + 1) * FF + n4);
        Wp[kp][n4 + 0] = __floats2half2_rn(w0.x, w1.x);
        Wp[kp][n4 + 1] = __floats2half2_rn(w0.y, w1.y);
        Wp[kp][n4 + 2] = __floats2half2_rn(w0.z, w1.z);
        Wp[kp][n4 + 3] = __floats2half2_rn(w0.w, w1.w);
    }
    __syncthreads();

    int warp = tid >> 5, lane = tid & 31;
    int gid = lane >> 2;
    int tig = lane & 3;
    int r_lo = r0 + warp * 16 + gid;
    int r_hi = r_lo + 8;
    bool vlo = r_lo < NN, vhi = r_hi < NN;
    const float2* plo = (const float2*)(X + (size_t)r_lo * FF);
    const float2* phi = (const float2*)(X + (size_t)r_hi * FF);
    int c2 = tig;

    float acc[16][4];
#pragma unroll
    for (int nt = 0; nt < 16; ++nt)
#pragma unroll
        for (int q = 0; q < 4; ++q) acc[nt][q] = 0.0f;

#pragma unroll
    for (int kk = 0; kk < 8; ++kk) {
        int kb = kk * 8;
        float2 z = make_float2(0.f, 0.f);
        float2 f0 = vlo ? plo[kb + c2]     : z;
        float2 f1 = vhi ? phi[kb + c2]     : z;
        float2 f2 = vlo ? plo[kb + c2 + 4] : z;
        float2 f3 = vhi ? phi[kb + c2 + 4] : z;
        unsigned a0 = f2h2(f0.x, f0.y);
        unsigned a1 = f2h2(f1.x, f1.y);
        unsigned a2 = f2h2(f2.x, f2.y);
        unsigned a3 = f2h2(f3.x, f3.y);
        int kp = kb + tig;
#pragma unroll
        for (int nt = 0; nt < 16; ++nt) {
            int n = nt * 8 + gid;
            unsigned b0 = *(unsigned*)&Wp[kp][n];
            unsigned b1 = *(unsigned*)&Wp[kp + 4][n];
            asm volatile(
                "mma.sync.aligned.m16n8k16.row.col.f32.f16.f16.f32 "
                "{%0,%1,%2,%3},{%4,%5,%6,%7},{%8,%9},{%0,%1,%2,%3};"
                : "+f"(acc[nt][0]), "+f"(acc[nt][1]), "+f"(acc[nt][2]), "+f"(acc[nt][3])
                : "r"(a0), "r"(a1), "r"(a2), "r"(a3), "r"(b0), "r"(b1));
        }
    }

#pragma unroll
    for (int nt = 0; nt < 16; ++nt) {
        int col = nt * 8 + tig * 2;
        if (vlo) {
            __half2 h = __floats2half2_rn(acc[nt][0], acc[nt][1]);
            *(__half2*)(g_xw + (size_t)r_lo * FF + col) = h;
        }
        if (vhi) {
            __half2 h = __floats2half2_rn(acc[nt][2], acc[nt][3]);
            *(__half2*)(g_xw + (size_t)r_hi * FF + col) = h;
        }
    }
}

// 8-feature fp16 fragment accumulate
__device__ __forceinline__ void acc_row8(float* acc, float n, int src, int fl) {
    uint4 r = *((const uint4*)(g_xw + (size_t)src * FF) + fl);
    float2 p0 = __half22float2(*reinterpret_cast<__half2*>(&r.x));
    float2 p1 = __half22float2(*reinterpret_cast<__half2*>(&r.y));
    float2 p2 = __half22float2(*reinterpret_cast<__half2*>(&r.z));
    float2 p3 = __half22float2(*reinterpret_cast<__half2*>(&r.w));
    acc[0] += n * p0.x; acc[1] += n * p0.y;
    acc[2] += n * p1.x; acc[3] += n * p1.y;
    acc[4] += n * p2.x; acc[5] += n * p2.y;
    acc[6] += n * p3.x; acc[7] += n * p3.y;
}

// ============ 5. CSR gather: 2 nodes/warp, meta prefetch ============
__global__ __launch_bounds__(256) void k_gather(const float* __restrict__ b) {
    int warp = threadIdx.x >> 5;
    int lane = threadIdx.x & 31;
    int half = lane >> 4;
    int fl   = lane & 15;
    int node = blockIdx.x * 16 + warp * 2 + half;
    if (node >= NN) return;
    int f8 = fl * 8;

    float acc[8];
    {
        float dv = g_dis[node];
        float d2 = dv * dv;
        uint4 r = *((const uint4*)(g_xw + (size_t)node * FF) + fl);
        float2 p0 = __half22float2(*reinterpret_cast<__half2*>(&r.x));
        float2 p1 = __half22float2(*reinterpret_cast<__half2*>(&r.y));
        float2 p2 = __half22float2(*reinterpret_cast<__half2*>(&r.z));
        float2 p3 = __half22float2(*reinterpret_cast<__half2*>(&r.w));
        float4 b0 = *(const float4*)(b + f8);
        float4 b1 = *(const float4*)(b + f8 + 4);
        acc[0] = b0.x + d2 * p0.x; acc[1] = b0.y + d2 * p0.y;
        acc[2] = b0.z + d2 * p1.x; acc[3] = b0.w + d2 * p1.y;
        acc[4] = b1.x + d2 * p2.x; acc[5] = b1.y + d2 * p2.y;
        acc[6] = b1.z + d2 * p3.x; acc[7] = b1.w + d2 * p3.y;
    }

    int j = g_off[node], j1 = g_off[node + 1];
    if ((j & 1) && j < j1) {
        int2 e = g_csr[j];
        acc_row8(acc, __int_as_float(e.y), e.x, fl);
        ++j;
    }
    int npairs = (j1 - j) >> 1;
    if (npairs > 0) {
        int4 m = *(const int4*)(g_csr + j);
        for (int p = 0; p < npairs; ++p) {
            int4 cur = m;
            if (p + 1 < npairs)
                m = *(const int4*)(g_csr + j + 2 * (p + 1));
            acc_row8(acc, __int_as_float(cur.y), cur.x, fl);
            acc_row8(acc, __int_as_float(cur.w), cur.z, fl);
        }
        j += 2 * npairs;
    }
    if (j < j1) {
        int2 e = g_csr[j];
        acc_row8(acc, __int_as_float(e.y), e.x, fl);
    }

    uint4 pk;
    pk.x = f2h2(acc[0], acc[1]);
    pk.y = f2h2(acc[2], acc[3]);
    pk.z = f2h2(acc[4], acc[5]);
    pk.w = f2h2(acc[6], acc[7]);
    *((uint4*)(g_hh + (size_t)node * FF) + fl) = pk;
}

// ============ 6. stats ============
__global__ void k_stats() {
    int g = blockIdx.y, c = blockIdx.x, f = threadIdx.x;
    int s = g_starts[g], e = g_starts[g + 1];
    int per = (e - s + gridDim.x - 1) / gridDim.x;
    int i0 = s + c * per;
    int i1 = min(i0 + per, e);
    float s1 = 0.0f, s2 = 0.0f;
    for (int i = i0; i < i1; ++i) {
        float v = __half2float(g_hh[(size_t)i * FF + f]);
        s1 += v; s2 += v * v;
    }
    if (i1 > i0) {
        atomicAdd(&g_sum[g * FF + f], s1);
        atomicAdd(&g_sq[g * FF + f], s2);
    }
}

// ============ 7. final: inline affine + normalize + ReLU + max ============
__global__ void k_final(const float* __restrict__ ms, const float* __restrict__ gnw,
                        const float* __restrict__ gnb,
                        float* __restrict__ out_h, float* __restrict__ out_flat) {
    int g = blockIdx.y, c = blockIdx.x, f = threadIdx.x;
    int s = g_starts[g], e = g_starts[g + 1];

    float cnt = fmaxf((float)(e - s), 1.0f);
    float mean = g_sum[g * FF + f] / cnt;
    float m2 = mean * ms[f];
    float var = g_sq[g * FF + f] / cnt - 2.0f * m2 * mean + m2 * m2;
    var = fmaxf(var, 0.0f);
    float rstd = rsqrtf(var + EPSV);
    float sc = gnw[f] * rstd;
    float sh = gnb[f] - sc * m2;

    int per = (e - s + gridDim.x - 1) / gridDim.x;
    int i0 = s + c * per;
    int i1 = min(i0 + per, e);
    float m = 0.0f;
    for (int i = i0; i < i1; ++i) {
        float hv = __half2float(g_hh[(size_t)i * FF + f]);
        float v = fmaxf(fmaf(hv, sc, sh), 0.0f);
        out_h[(size_t)i * FF + f] = v;
        m = fmaxf(m, v);
    }
    if (i1 > i0) atomicMax((int*)&out_flat[g * FF + f], __float_as_int(m));
}

// ---------------------------------------------------------------------------
extern "C" void kernel_launch(void* const* d_in, const int* in_sizes, int n_in,
                              void* d_out, int out_size) {
    const float* X   = (const float*)d_in[0];
    const int*   ei  = (const int*)d_in[1];
    const int*   bat = (const int*)d_in[2];
    const float* ew  = (const float*)d_in[3];
    const float* W   = (const float*)d_in[4];
    const float* b   = (const float*)d_in[5];
    const float* gnw = (const float*)d_in[6];
    const float* gnb = (const float*)d_in[7];
    const float* gms = (const float*)d_in[8];
    float* out = (float*)d_out;

    k_pre<<<INIT_B + ZERO_B + BOUNDS_B, 256>>>(bat, out + OUT_FLAT);
    k_degtail<<<DEG_B + TAIL_B, 256>>>(ei, ew, bat, out);

    k_scan<<<SCAN_B, SCAN_T>>>();

    k_csrgemm<<<GEMM_B + CSR_B, 256>>>(X, W, ei, ew);

    k_gather<<<(NN + 15) / 16, 256>>>(b);

    dim3 sgrid(16, GG);
    k_stats<<<sgrid, FF>>>();

    dim3 fgrid(32, GG);
    k_final<<<fgrid, FF>>>(gms, gnw, gnb, out, out + OUT_FLAT);
}

// round 16
// speedup vs baseline: 1.1364x; 1.0642x over previous
#include <cuda_runtime.h>
#include <cuda_fp16.h>
#include <cstdint>

#define NN 100000
#define NE 1600000
#define FF 128
#define GG 64
#define EPSV 1e-5f

#define OUT_FLAT ((size_t)NN * FF)
#define OUT_EI   (OUT_FLAT + (size_t)GG * FF)
#define OUT_EW   (OUT_EI + (size_t)2 * NE)
#define OUT_B    (OUT_EW + (size_t)NE)

#define SCAN_B 98
#define SCAN_T 256
#define SCAN_I 4

#define FIXS 268435456.0f               /* 2^28 */
#define FIXR 3.7252902984619140625e-9f /* 2^-28 */

#define INIT_B   391
#define ZERO_B   32
#define BOUNDS_B 391
#define DEG_B    6250
#define TAILV    1225000
#define TAIL_B   4786
#define GEMM_B   1563                    /* ceil(NN/64): 64 rows per block now */
#define CSR_B    6250

// Scratch
__device__ unsigned long long g_pack[NN];
__device__ unsigned short g_slot[NE];
__device__ float  g_dis[NN];
__device__ int    g_cnt[NN];
__device__ int    g_off[NN + 1];
__device__ int    g_bsum[SCAN_B];
__device__ int2   g_csr[NE];                // {src, norm bits}
__device__ __half g_xw[(size_t)NN * FF];
__device__ __half g_hh[(size_t)NN * FF];
__device__ int    g_starts[GG + 1];
__device__ float  g_sum[GG * FF];
__device__ float  g_sq[GG * FF];

__device__ __forceinline__ unsigned f2h2(float a, float b) {
    __half2 h = __floats2half2_rn(a, b);
    return *(unsigned*)&h;
}

// ============ 1. fused: init ∥ zero ∥ bounds ============
__global__ void k_pre(const int* __restrict__ batch, float* __restrict__ out_flat) {
    int blk = blockIdx.x;
    if (blk < INIT_B) {
        int i = blk * 256 + threadIdx.x;
        if (i < NN) g_pack[i] = (unsigned long long)(1u << 28);
    } else if (blk < INIT_B + ZERO_B) {
        int i = (blk - INIT_B) * 256 + threadIdx.x;
        g_sum[i] = 0.0f; g_sq[i] = 0.0f; out_flat[i] = 0.0f;
    } else {
        int i = (blk - INIT_B - ZERO_B) * 256 + threadIdx.x;
        if (i >= NN) return;
        int bv = batch[i];
        int prev = (i == 0) ? -1 : batch[i - 1];
        for (int g = prev + 1; g <= bv; ++g) g_starts[g] = i;
        if (i == NN - 1)
            for (int g = bv + 1; g <= GG; ++g) g_starts[g] = NN;
    }
}

// ============ 2. fused: deg ∥ vectorized tail ============
__global__ void k_degtail(const int* __restrict__ ei, const float* __restrict__ ew,
                          const int* __restrict__ batch, float* __restrict__ out) {
    int blk = blockIdx.x;
    if (blk < DEG_B) {
        int e = blk * 256 + threadIdx.x;
        int d = ei[NE + e];
        unsigned long long q = (unsigned long long)__float2uint_rn(ew[e] * FIXS);
        unsigned long long old = atomicAdd(&g_pack[d], (1ull << 40) | q);
        g_slot[e] = (unsigned short)(old >> 40);
    } else {
        int vt = (blk - DEG_B) * 256 + threadIdx.x;
        if (vt >= TAILV) return;
        if (vt < 800000) {
            int j = vt * 4;
            int4 v = *(const int4*)(ei + j);
            float4 o = make_float4((float)v.x, (float)v.y, (float)v.z, (float)v.w);
            *(float4*)(out + OUT_EI + j) = o;
        } else if (vt < 1200000) {
            int j = (vt - 800000) * 4;
            *(float4*)(out + OUT_EW + j) = *(const float4*)(ew + j);
        } else {
            int j = (vt - 1200000) * 4;
            int4 v = *(const int4*)(batch + j);
            float4 o = make_float4((float)v.x, (float)v.y, (float)v.z, (float)v.w);
            *(float4*)(out + OUT_B + j) = o;
        }
    }
}

// ============ 3a. per-block reduce + unpack ============
__global__ void k_scan1() {
    __shared__ int sh[SCAN_T];
    int t = threadIdx.x;
    int base = blockIdx.x * SCAN_T * SCAN_I + t * SCAN_I;
    int s = 0;
#pragma unroll
    for (int k = 0; k < SCAN_I; ++k) {
        int i = base + k;
        if (i < NN) {
            unsigned long long p = g_pack[i];
            int c = (int)(p >> 40);
            g_cnt[i] = c;
            g_dis[i] = rsqrtf((float)(p & 0xFFFFFFFFFFull) * FIXR);
            s += c;
        }
    }
    sh[t] = s;
    __syncthreads();
    for (int off = SCAN_T / 2; off > 0; off >>= 1) {
        if (t < off) sh[t] += sh[t + off];
        __syncthreads();
    }
    if (t == 0) g_bsum[blockIdx.x] = sh[0];
}

// ============ 3b. scan3 with integrated block-sum scan ============
__global__ void k_scan3() {
    __shared__ int sh[SCAN_T];
    __shared__ int sb[SCAN_T];
    int t = threadIdx.x;

    sb[t] = (t < SCAN_B) ? g_bsum[t] : 0;
    __syncthreads();
    for (int off = 1; off < SCAN_T; off <<= 1) {
        int v = (t >= off) ? sb[t - off] : 0;
        __syncthreads();
        sb[t] += v;
        __syncthreads();
    }
    int block_base = sb[blockIdx.x] - g_bsum[blockIdx.x];

    int base = blockIdx.x * SCAN_T * SCAN_I + t * SCAN_I;
    int c[SCAN_I];
    int s = 0;
#pragma unroll
    for (int k = 0; k < SCAN_I; ++k) {
        int i = base + k;
        c[k] = (i < NN) ? g_cnt[i] : 0;
        s += c[k];
    }
    sh[t] = s;
    __syncthreads();
    for (int off = 1; off < SCAN_T; off <<= 1) {
        int v = (t >= off) ? sh[t - off] : 0;
        __syncthreads();
        sh[t] += v;
        __syncthreads();
    }
    int run = block_base + sh[t] - s;
#pragma unroll
    for (int k = 0; k < SCAN_I; ++k) {
        int i = base + k;
        if (i < NN) g_off[i] = run;
        run += c[k];
    }
    if (blockIdx.x == 0 && t == 0) g_off[NN] = NE;
}

// ============ 4. fused: low-reg HMMA gemm ∥ compact csr fill ============
// GEMM: 64 rows per block; warp pair shares 16 rows, splits 128 cols in half.
// acc[8][4] = 32 regs/thread -> higher occupancy for the fused CSR half.
__global__ __launch_bounds__(256) void k_csrgemm(const float* __restrict__ X,
                                                 const float* __restrict__ W,
                                                 const int* __restrict__ ei,
                                                 const float* __restrict__ ew) {
    __shared__ __half2 Wp[64][136];
    int blk = blockIdx.x;
    int tid = threadIdx.x;

    if (blk >= GEMM_B) {
        int e = (blk - GEMM_B) * 256 + tid;
        if (e < NE) {
            int s = ei[e];
            int d = ei[NE + e];
            float nrm = g_dis[s] * ew[e] * g_dis[d];
            int pos = g_off[d] + (int)g_slot[e];
            g_csr[pos] = make_int2(s, __float_as_int(nrm));
        }
        return;
    }

    int r0 = blk * 64;
    for (int idx = tid; idx < 64 * 32; idx += 256) {
        int kp = idx >> 5;
        int n4 = (idx & 31) * 4;
        float4 w0 = *(const float4*)(W + (size_t)(2 * kp) * FF + n4);
        float4 w1 = *(const float4*)(W + (size_t)(2 * kp + 1) * FF + n4);
        Wp[kp][n4 + 0] = __floats2half2_rn(w0.x, w1.x);
        Wp[kp][n4 + 1] = __floats2half2_rn(w0.y, w1.y);
        Wp[kp][n4 + 2] = __floats2half2_rn(w0.z, w1.z);
        Wp[kp][n4 + 3] = __floats2half2_rn(w0.w, w1.w);
    }
    __syncthreads();

    int warp = tid >> 5, lane = tid & 31;
    int gid = lane >> 2;
    int tig = lane & 3;
    int rowgrp = warp >> 1;                // 0..3: 16-row group
    int colhalf = (warp & 1) * 64;         // 0 or 64
    int r_lo = r0 + rowgrp * 16 + gid;
    int r_hi = r_lo + 8;
    bool vlo = r_lo < NN, vhi = r_hi < NN;
    const float2* plo = (const float2*)(X + (size_t)r_lo * FF);
    const float2* phi = (const float2*)(X + (size_t)r_hi * FF);
    int c2 = tig;

    float acc[8][4];
#pragma unroll
    for (int nt = 0; nt < 8; ++nt)
#pragma unroll
        for (int q = 0; q < 4; ++q) acc[nt][q] = 0.0f;

#pragma unroll
    for (int kk = 0; kk < 8; ++kk) {
        int kb = kk * 8;
        float2 z = make_float2(0.f, 0.f);
        float2 f0 = vlo ? plo[kb + c2]     : z;
        float2 f1 = vhi ? phi[kb + c2]     : z;
        float2 f2 = vlo ? plo[kb + c2 + 4] : z;
        float2 f3 = vhi ? phi[kb + c2 + 4] : z;
        unsigned a0 = f2h2(f0.x, f0.y);
        unsigned a1 = f2h2(f1.x, f1.y);
        unsigned a2 = f2h2(f2.x, f2.y);
        unsigned a3 = f2h2(f3.x, f3.y);
        int kp = kb + tig;
#pragma unroll
        for (int nt = 0; nt < 8; ++nt) {
            int n = colhalf + nt * 8 + gid;
            unsigned b0 = *(unsigned*)&Wp[kp][n];
            unsigned b1 = *(unsigned*)&Wp[kp + 4][n];
            asm volatile(
                "mma.sync.aligned.m16n8k16.row.col.f32.f16.f16.f32 "
                "{%0,%1,%2,%3},{%4,%5,%6,%7},{%8,%9},{%0,%1,%2,%3};"
                : "+f"(acc[nt][0]), "+f"(acc[nt][1]), "+f"(acc[nt][2]), "+f"(acc[nt][3])
                : "r"(a0), "r"(a1), "r"(a2), "r"(a3), "r"(b0), "r"(b1));
        }
    }

#pragma unroll
    for (int nt = 0; nt < 8; ++nt) {
        int col = colhalf + nt * 8 + tig * 2;
        if (vlo) {
            __half2 h = __floats2half2_rn(acc[nt][0], acc[nt][1]);
            *(__half2*)(g_xw + (size_t)r_lo * FF + col) = h;
        }
        if (vhi) {
            __half2 h = __floats2half2_rn(acc[nt][2], acc[nt][3]);
            *(__half2*)(g_xw + (size_t)r_hi * FF + col) = h;
        }
    }
}

// 8-feature fp16 fragment accumulate
__device__ __forceinline__ void acc_row8(float* acc, float n, int src, int fl) {
    uint4 r = *((const uint4*)(g_xw + (size_t)src * FF) + fl);
    float2 p0 = __half22float2(*reinterpret_cast<__half2*>(&r.x));
    float2 p1 = __half22float2(*reinterpret_cast<__half2*>(&r.y));
    float2 p2 = __half22float2(*reinterpret_cast<__half2*>(&r.z));
    float2 p3 = __half22float2(*reinterpret_cast<__half2*>(&r.w));
    acc[0] += n * p0.x; acc[1] += n * p0.y;
    acc[2] += n * p1.x; acc[3] += n * p1.y;
    acc[4] += n * p2.x; acc[5] += n * p2.y;
    acc[6] += n * p3.x; acc[7] += n * p3.y;
}

// ============ 5. CSR gather: 2 nodes/warp, 16 lanes/node (R12 body) ============
__global__ __launch_bounds__(256) void k_gather(const float* __restrict__ b) {
    int warp = threadIdx.x >> 5;
    int lane = threadIdx.x & 31;
    int half = lane >> 4;
    int fl   = lane & 15;
    int node = blockIdx.x * 16 + warp * 2 + half;
    if (node >= NN) return;
    int f8 = fl * 8;

    float acc[8];
    {
        float dv = g_dis[node];
        float d2 = dv * dv;
        uint4 r = *((const uint4*)(g_xw + (size_t)node * FF) + fl);
        float2 p0 = __half22float2(*reinterpret_cast<__half2*>(&r.x));
        float2 p1 = __half22float2(*reinterpret_cast<__half2*>(&r.y));
        float2 p2 = __half22float2(*reinterpret_cast<__half2*>(&r.z));
        float2 p3 = __half22float2(*reinterpret_cast<__half2*>(&r.w));
        float4 b0 = *(const float4*)(b + f8);
        float4 b1 = *(const float4*)(b + f8 + 4);
        acc[0] = b0.x + d2 * p0.x; acc[1] = b0.y + d2 * p0.y;
        acc[2] = b0.z + d2 * p1.x; acc[3] = b0.w + d2 * p1.y;
        acc[4] = b1.x + d2 * p2.x; acc[5] = b1.y + d2 * p2.y;
        acc[6] = b1.z + d2 * p3.x; acc[7] = b1.w + d2 * p3.y;
    }

    int j = g_off[node], j1 = g_off[node + 1];
    if ((j & 1) && j < j1) {
        int2 e = g_csr[j];
        acc_row8(acc, __int_as_float(e.y), e.x, fl);
        ++j;
    }
    for (; j + 4 <= j1; j += 4) {
        int4 m0 = *(const int4*)(g_csr + j);
        int4 m1 = *(const int4*)(g_csr + j + 2);
        acc_row8(acc, __int_as_float(m0.y), m0.x, fl);
        acc_row8(acc, __int_as_float(m0.w), m0.z, fl);
        acc_row8(acc, __int_as_float(m1.y), m1.x, fl);
        acc_row8(acc, __int_as_float(m1.w), m1.z, fl);
    }
    if (j + 2 <= j1) {
        int4 m0 = *(const int4*)(g_csr + j);
        acc_row8(acc, __int_as_float(m0.y), m0.x, fl);
        acc_row8(acc, __int_as_float(m0.w), m0.z, fl);
        j += 2;
    }
    if (j < j1) {
        int2 e = g_csr[j];
        acc_row8(acc, __int_as_float(e.y), e.x, fl);
    }

    uint4 pk;
    pk.x = f2h2(acc[0], acc[1]);
    pk.y = f2h2(acc[2], acc[3]);
    pk.z = f2h2(acc[4], acc[5]);
    pk.w = f2h2(acc[6], acc[7]);
    *((uint4*)(g_hh + (size_t)node * FF) + fl) = pk;
}

// ============ 6. stats ============
__global__ void k_stats() {
    int g = blockIdx.y, c = blockIdx.x, f = threadIdx.x;
    int s = g_starts[g], e = g_starts[g + 1];
    int per = (e - s + gridDim.x - 1) / gridDim.x;
    int i0 = s + c * per;
    int i1 = min(i0 + per, e);
    float s1 = 0.0f, s2 = 0.0f;
    for (int i = i0; i < i1; ++i) {
        float v = __half2float(g_hh[(size_t)i * FF + f]);
        s1 += v; s2 += v * v;
    }
    if (i1 > i0) {
        atomicAdd(&g_sum[g * FF + f], s1);
        atomicAdd(&g_sq[g * FF + f], s2);
    }
}

// ============ 7. final: inline affine + normalize + ReLU + max ============
__global__ void k_final(const float* __restrict__ ms, const float* __restrict__ gnw,
                        const float* __restrict__ gnb,
                        float* __restrict__ out_h, float* __restrict__ out_flat) {
    int g = blockIdx.y, c = blockIdx.x, f = threadIdx.x;
    int s = g_starts[g], e = g_starts[g + 1];

    float cnt = fmaxf((float)(e - s), 1.0f);
    float mean = g_sum[g * FF + f] / cnt;
    float m2 = mean * ms[f];
    float var = g_sq[g * FF + f] / cnt - 2.0f * m2 * mean + m2 * m2;
    var = fmaxf(var, 0.0f);
    float rstd = rsqrtf(var + EPSV);
    float sc = gnw[f] * rstd;
    float sh = gnb[f] - sc * m2;

    int per = (e - s + gridDim.x - 1) / gridDim.x;
    int i0 = s + c * per;
    int i1 = min(i0 + per, e);
    float m = 0.0f;
    for (int i = i0; i < i1; ++i) {
        float hv = __half2float(g_hh[(size_t)i * FF + f]);
        float v = fmaxf(fmaf(hv, sc, sh), 0.0f);
        out_h[(size_t)i * FF + f] = v;
        m = fmaxf(m, v);
    }
    if (i1 > i0) atomicMax((int*)&out_flat[g * FF + f], __float_as_int(m));
}

// ---------------------------------------------------------------------------
extern "C" void kernel_launch(void* const* d_in, const int* in_sizes, int n_in,
                              void* d_out, int out_size) {
    const float* X   = (const float*)d_in[0];
    const int*   ei  = (const int*)d_in[1];
    const int*   bat = (const int*)d_in[2];
    const float* ew  = (const float*)d_in[3];
    const float* W   = (const float*)d_in[4];
    const float* b   = (const float*)d_in[5];
    const float* gnw = (const float*)d_in[6];
    const float* gnb = (const float*)d_in[7];
    const float* gms = (const float*)d_in[8];
    float* out = (float*)d_out;

    k_pre<<<INIT_B + ZERO_B + BOUNDS_B, 256>>>(bat, out + OUT_FLAT);
    k_degtail<<<DEG_B + TAIL_B, 256>>>(ei, ew, bat, out);

    k_scan1<<<SCAN_B, SCAN_T>>>();
    k_scan3<<<SCAN_B, SCAN_T>>>();

    k_csrgemm<<<GEMM_B + CSR_B, 256>>>(X, W, ei, ew);

    k_gather<<<(NN + 15) / 16, 256>>>(b);

    dim3 sgrid(16, GG);
    k_stats<<<sgrid, FF>>>();

    dim3 fgrid(32, GG);
    k_final<<<fgrid, FF>>>(gms, gnw, gnb, out, out + OUT_FLAT);
}